// round 13
// baseline (speedup 1.0000x reference)
#include <cuda_runtime.h>
#include <cstdint>

#define SEQ_LEN  120
#define BATCH    2048
#define INPUT    6
#define HID      64
#define GATES    256
#define LAYERS   4
#define TLEN     120
#define NB       16
#define NCTA     (BATCH / NB)   // 128
#define NTHR     256

#define UNIT_F4     4096                 // 64 k x 64 hh float4 = 64KB
#define UNIT_BYTES  (UNIT_F4 * 16)
#define NBUF        3
#define UPS         7                    // units per step
#define UNITS_TOTAL (240 * UPS)          // 1680
#define RES_F4      512                  // W0: 8 k x 64 hh = 8KB
#define RES_BYTES   (RES_F4 * 16)

typedef unsigned long long ull;

// per-phase periodic stream: [7 units][64 k][64 hh] float4 {wi,wf,wg,wo}
// unit map: u0=Whh L0; u1=Whh L1; u2=Wih L1; u3=Whh L2; u4=Wih L2; u5=Whh L3; u6=Wih L3
__device__ float4 g_stream_e[UPS * UNIT_F4];
__device__ float4 g_stream_d[UPS * UNIT_F4];
__device__ float4 g_res_e[RES_F4];
__device__ float4 g_res_d[RES_F4];

__global__ void lstm36206574305735_pack(
    const float* __restrict__ eW0, const float* __restrict__ eWih,
    const float* __restrict__ eWhh, const float* __restrict__ dW0,
    const float* __restrict__ dWih, const float* __restrict__ dWhh)
{
    const int PER = UPS * UNIT_F4 + RES_F4;
    const int tot = 2 * PER;
    for (int idx = blockIdx.x * blockDim.x + threadIdx.x; idx < tot;
         idx += gridDim.x * blockDim.x) {
        int p = idx / PER;
        int r = idx % PER;
        const float* W0  = p ? dW0  : eW0;
        const float* Wih = p ? dWih : eWih;
        const float* Whh = p ? dWhh : eWhh;
        if (r < UPS * UNIT_F4) {
            int su = r / UNIT_F4;
            int rr = r % UNIT_F4;
            int k  = rr / HID;
            int hh = rr % HID;
            const float* W;
            if (su == 0)          W = Whh;                                  // Whh L0
            else if (su & 1)      W = Whh + (size_t)((su + 1) / 2) * GATES * HID;
            else                  W = Wih + (size_t)(su / 2 - 1) * GATES * HID;
            float4 v;
            v.x = W[(0 * HID + hh) * HID + k];
            v.y = W[(1 * HID + hh) * HID + k];
            v.z = W[(2 * HID + hh) * HID + k];
            v.w = W[(3 * HID + hh) * HID + k];
            (p ? g_stream_d : g_stream_e)[r] = v;
        } else {
            int q  = r - UPS * UNIT_F4;
            int k  = q / HID;
            int hh = q % HID;
            float4 v = make_float4(0.f, 0.f, 0.f, 0.f);
            if (k < INPUT) {
                v.x = W0[(0 * HID + hh) * INPUT + k];
                v.y = W0[(1 * HID + hh) * INPUT + k];
                v.z = W0[(2 * HID + hh) * INPUT + k];
                v.w = W0[(3 * HID + hh) * INPUT + k];
            }
            (p ? g_res_d : g_res_e)[q] = v;
        }
    }
}

// ---- helpers ----------------------------------------------------------------
__device__ __forceinline__ void ffma2(ull& d, ull a, ull b) {
    asm("fma.rn.f32x2 %0, %1, %2, %0;" : "+l"(d) : "l"(a), "l"(b));
}
__device__ __forceinline__ ull dup2(float a) {
    ull v; asm("mov.b64 %0, {%1, %1};" : "=l"(v) : "f"(a)); return v;
}
__device__ __forceinline__ float2 unpk(ull v) {
    float2 r; asm("mov.b64 {%0, %1}, %2;" : "=f"(r.x), "=f"(r.y) : "l"(v)); return r;
}
__device__ __forceinline__ float fsig(float x) {
    return __fdividef(1.0f, 1.0f + __expf(-x));
}
__device__ __forceinline__ float ftanh_(float x) {
    return 2.0f * fsig(2.0f * x) - 1.0f;
}
__device__ __forceinline__ uint32_t smem_u32(const void* p) {
    uint32_t a;
    asm("{ .reg .u64 t; cvta.to.shared.u64 t, %1; cvt.u32.u64 %0, t; }"
        : "=r"(a) : "l"(p));
    return a;
}
__device__ __forceinline__ void cpa16(uint32_t dst, const void* src) {
    asm volatile("cp.async.cg.shared.global [%0], [%1], 16;"
                 :: "r"(dst), "l"(src) : "memory");
}
#define CPA_COMMIT() asm volatile("cp.async.commit_group;" ::: "memory")
#define CPA_WAIT1()  asm volatile("cp.async.wait_group 1;" ::: "memory")

// proven gemv mix: per k = 2 LDS.128 + 4 dup MOVs + 8 FFMA2
template <int K>
__device__ __forceinline__ void gemv_s(const float4* __restrict__ wslot,
                                       const float* __restrict__ hs,
                                       int hh, int bg, ull acc[8])
{
#pragma unroll 8
    for (int k = 0; k < K; k++) {
        float4 w4 = wslot[k * HID + hh];
        ulonglong2 hv = *(const ulonglong2*)(hs + k * 16 + bg * 4);
        ull wi = dup2(w4.x), wf = dup2(w4.y), wg = dup2(w4.z), wo = dup2(w4.w);
        ffma2(acc[0], wi, hv.x); ffma2(acc[1], wi, hv.y);
        ffma2(acc[2], wf, hv.x); ffma2(acc[3], wf, hv.y);
        ffma2(acc[4], wg, hv.x); ffma2(acc[5], wg, hv.y);
        ffma2(acc[6], wo, hv.x); ffma2(acc[7], wo, hv.y);
    }
}

// ---- smem layout (bytes) ------------------------------------------------------
#define BUFS_B   0
#define BUFS_SZ  (NBUF * UNIT_BYTES)      // 196608
#define RES_B    BUFS_SZ                  // +8192
#define FB_B     (RES_B + RES_BYTES)      // 204800
// floats from FB_B
#define HD_F     0                         // [4][64][16]
#define SZ_HD    (LAYERS * HID * 16)       // 4096
#define IND_F    (HD_F + SZ_HD)            // [8][16], rows 6,7 zero
#define SZ_IND   (8 * 16)
#define LW_F     (IND_F + SZ_IND)
#define LB_F     (LW_F + HID * INPUT)
#define BIAS_F   (LB_F + 8)                // float4[2][4][64] = 2048 floats
#define SZ_BIAS  (2 * LAYERS * HID * 4)
#define SMEM_TOTAL_B (FB_B + (BIAS_F + SZ_BIAS) * 4)   // 231456

__global__ void __launch_bounds__(NTHR, 1)
lstm36206574305735_main(const float* __restrict__ x,
                        const float* __restrict__ eB,
                        const float* __restrict__ dB,
                        const float* __restrict__ linW,
                        const float* __restrict__ linB,
                        float* __restrict__ out)
{
    extern __shared__ char sm[];
    const uint32_t base_u = smem_u32(sm);
    float* fb   = (float*)(sm + FB_B);
    float* hd   = fb + HD_F;
    float* ind  = fb + IND_F;
    float* lw_s = fb + LW_F;
    float* lb_s = fb + LB_F;
    float4* bias = (float4*)(fb + BIAS_F);

    const int tid = threadIdx.x;
    const int hh  = tid >> 2;
    const int bg  = tid & 3;
    const int b0  = blockIdx.x * NB;

    // ---- cp.async streamers ----
    auto issue_unit = [&](int u) {
        if (u < UNITS_TOTAL) {
            const float4* src = (u < 120 * UPS ? g_stream_e : g_stream_d)
                                + (size_t)(u % UPS) * UNIT_F4;
            uint32_t dst = base_u + (uint32_t)(u % NBUF) * UNIT_BYTES + tid * 16;
#pragma unroll
            for (int j = 0; j < 16; j++)
                cpa16(dst + j * 4096, src + tid + j * 256);
        }
    };
    auto issue_res = [&](int p) {
        const float4* src = (p ? g_res_d : g_res_e);
        uint32_t dst = base_u + (uint32_t)RES_B + tid * 16;
        cpa16(dst,        src + tid);
        cpa16(dst + 4096, src + tid + 256);
    };
    auto bufp = [&](int u) -> const float4* {
        return (const float4*)(sm + (size_t)(u % NBUF) * UNIT_BYTES);
    };

    // ---- init smem data ----
    for (int i = tid; i < SZ_HD; i += NTHR) hd[i] = 0.0f;
    for (int i = tid; i < SZ_IND; i += NTHR) ind[i] = 0.0f;
    for (int i = tid; i < HID * INPUT; i += NTHR) {
        int h2 = i / INPUT, ii2 = i % INPUT;
        lw_s[h2 * INPUT + ii2] = linW[ii2 * HID + h2];
    }
    if (tid < INPUT) lb_s[tid] = linB[tid];
    for (int u = tid; u < 2 * LAYERS * HID; u += NTHR) {
        int phase = u >> 8, l = (u >> 6) & 3, hx = u & 63;
        const float* B = phase ? dB : eB;
        bias[u] = make_float4(B[l * GATES + hx],
                              B[l * GATES + HID + hx],
                              B[l * GATES + 2 * HID + hx],
                              B[l * GATES + 3 * HID + hx]);
    }

    // prefetch: group1 = res + unit0, group2 = unit1
    issue_res(0);
    issue_unit(0);
    CPA_COMMIT();
    issue_unit(1);
    CPA_COMMIT();
    CPA_WAIT1();          // res + unit0 complete
    __syncthreads();

    float c_reg[LAYERS][4];
#pragma unroll
    for (int l = 0; l < LAYERS; l++)
#pragma unroll
        for (int bi = 0; bi < 4; bi++) c_reg[l][bi] = 0.0f;

    const int  bb  = tid / INPUT;
    const int  ii  = tid % INPUT;
    const bool isx = tid < INPUT * NB;
    float xreg = 0.0f;
    if (isx) xreg = x[(size_t)(b0 + bb) * INPUT + ii];

    auto initb = [&](int p, int l, ull acc[8]) {
        float4 bv = bias[(p * LAYERS + l) * HID + hh];
        acc[0] = acc[1] = dup2(bv.x);
        acc[2] = acc[3] = dup2(bv.y);
        acc[4] = acc[5] = dup2(bv.z);
        acc[6] = acc[7] = dup2(bv.w);
    };
    auto epi = [&](int l, ull acc[8]) {
        float2 ai0 = unpk(acc[0]), ai1 = unpk(acc[1]);
        float2 af0 = unpk(acc[2]), af1 = unpk(acc[3]);
        float2 ag0 = unpk(acc[4]), ag1 = unpk(acc[5]);
        float2 ao0 = unpk(acc[6]), ao1 = unpk(acc[7]);
        float ai[4] = {ai0.x, ai0.y, ai1.x, ai1.y};
        float af[4] = {af0.x, af0.y, af1.x, af1.y};
        float ag[4] = {ag0.x, ag0.y, ag1.x, ag1.y};
        float ao[4] = {ao0.x, ao0.y, ao1.x, ao1.y};
        float hout[4];
#pragma unroll
        for (int bi = 0; bi < 4; bi++) {
            float c = fmaf(fsig(af[bi]), c_reg[l][bi],
                           fsig(ai[bi]) * ftanh_(ag[bi]));
            c_reg[l][bi] = c;
            hout[bi] = fsig(ao[bi]) * ftanh_(c);
        }
        float* hrow = hd + (l * HID + hh) * 16 + bg * 4;
        *(float4*)hrow = make_float4(hout[0], hout[1], hout[2], hout[3]);
    };
    // close a segment: prefetch unit u+2, guarantee u+1 resident, sync
    auto seg_tail = [&](int u, bool res_reload) {
        issue_unit(u + 2);
        if (res_reload) issue_res(1);   // bundled into this commit group
        CPA_COMMIT();
        CPA_WAIT1();
        __syncthreads();
    };

    int u = 0;
    for (int t = 0; t < SEQ_LEN + TLEN; t++) {
        const int p = (t >= SEQ_LEN) ? 1 : 0;

        // ---- S0: [proj(t-1) / ind load] + Whh L0 ----
        if (isx) {
            if (t > SEQ_LEN) {
                const float* htop = hd + 3 * 1024;
                float v = lb_s[ii];
#pragma unroll 8
                for (int h4 = 0; h4 < HID; h4++)
                    v += lw_s[h4 * INPUT + ii] * htop[h4 * 16 + bb];
                out[((size_t)(t - 1 - SEQ_LEN) * BATCH + b0 + bb) * INPUT + ii] = v;
                ind[ii * 16 + bb] = v;
            } else if (t < SEQ_LEN) {
                ind[ii * 16 + bb] = xreg;
                if (t + 1 < SEQ_LEN)
                    xreg = x[((size_t)(t + 1) * BATCH + b0 + bb) * INPUT + ii];
            }
        }
        ull acc[8];
        initb(p, 0, acc);
        gemv_s<64>(bufp(u), hd, hh, bg, acc);
        seg_tail(u, false); u++;

        // ---- S1: W0(res) + epi0 ; Whh L1 ----
        gemv_s<8>((const float4*)(sm + RES_B), ind, hh, bg, acc);
        epi(0, acc);
        initb(p, 1, acc);
        gemv_s<64>(bufp(u), hd + 1024, hh, bg, acc);
        seg_tail(u, false); u++;

        // ---- S2: Wih L1 over new h0 + epi1 ----
        gemv_s<64>(bufp(u), hd, hh, bg, acc);
        epi(1, acc);
        seg_tail(u, t == SEQ_LEN - 1); u++;   // reload decoder W0 here

        // ---- S3: Whh L2 ----
        initb(p, 2, acc);
        gemv_s<64>(bufp(u), hd + 2 * 1024, hh, bg, acc);
        seg_tail(u, false); u++;

        // ---- S4: Wih L2 over new h1 + epi2 ----
        gemv_s<64>(bufp(u), hd + 1024, hh, bg, acc);
        epi(2, acc);
        seg_tail(u, false); u++;

        // ---- S5: Whh L3 ----
        initb(p, 3, acc);
        gemv_s<64>(bufp(u), hd + 3 * 1024, hh, bg, acc);
        seg_tail(u, false); u++;

        // ---- S6: Wih L3 over new h2 + epi3 ----
        gemv_s<64>(bufp(u), hd + 2 * 1024, hh, bg, acc);
        epi(3, acc);
        seg_tail(u, false); u++;
    }

    // tail: projection for the final decoder step (t = 239)
    if (isx) {
        const float* htop = hd + 3 * 1024;
        float v = lb_s[ii];
#pragma unroll 8
        for (int h4 = 0; h4 < HID; h4++)
            v += lw_s[h4 * INPUT + ii] * htop[h4 * 16 + bb];
        out[((size_t)(TLEN - 1) * BATCH + b0 + bb) * INPUT + ii] = v;
    }
}

extern "C" void kernel_launch(void* const* d_in, const int* in_sizes, int n_in,
                              void* d_out, int out_size)
{
    const float* x    = (const float*)d_in[0];
    const float* eW0  = (const float*)d_in[1];
    const float* eWih = (const float*)d_in[2];
    const float* eWhh = (const float*)d_in[3];
    const float* eB   = (const float*)d_in[4];
    const float* dW0  = (const float*)d_in[5];
    const float* dWih = (const float*)d_in[6];
    const float* dWhh = (const float*)d_in[7];
    const float* dB   = (const float*)d_in[8];
    const float* linW = (const float*)d_in[9];
    const float* linB = (const float*)d_in[10];
    float* out = (float*)d_out;

    lstm36206574305735_pack<<<228, 256>>>(eW0, eWih, eWhh, dW0, dWih, dWhh);

    cudaFuncSetAttribute(lstm36206574305735_main,
                         cudaFuncAttributeMaxDynamicSharedMemorySize, SMEM_TOTAL_B);
    lstm36206574305735_main<<<NCTA, NTHR, SMEM_TOTAL_B>>>(x, eB, dB, linW, linB, out);
}

// round 15
// speedup vs baseline: 1.0449x; 1.0449x over previous
#include <cuda_runtime.h>
#include <cstdint>

#define SEQ_LEN  120
#define BATCH    2048
#define INPUT    6
#define HID      64
#define GATES    256
#define LAYERS   4
#define TLEN     120
#define NB       16
#define NCTA     (BATCH / NB)   // 128
#define NTHR     256

#define CHUNK_ROWS 32
#define CHUNK_F4   (CHUNK_ROWS * HID)     // 2048 float4
#define CHUNK_BYTES (CHUNK_F4 * 16)       // 32768
#define NSLOT      5
#define CPS        15
#define TOTALC     (240 * CPS)

typedef unsigned long long ull;

// ---- flat periodic weight streams: [15 chunks][32 k][64 hh] float4{i,f,g,o}
__device__ float4 g_stream_e[CPS * CHUNK_F4];
__device__ float4 g_stream_d[CPS * CHUNK_F4];

__global__ void lstm36206574305735_pack(
    const float* __restrict__ eW0, const float* __restrict__ eWih,
    const float* __restrict__ eWhh, const float* __restrict__ dW0,
    const float* __restrict__ dWih, const float* __restrict__ dWhh)
{
    const int tot = 2 * CPS * CHUNK_F4;
    for (int idx = blockIdx.x * blockDim.x + threadIdx.x; idx < tot;
         idx += gridDim.x * blockDim.x) {
        int p  = idx / (CPS * CHUNK_F4);
        int r  = idx % (CPS * CHUNK_F4);
        int c  = r / CHUNK_F4;
        int rr = r % CHUNK_F4;
        int kc = rr / HID;
        int hh = rr % HID;
        const float* W0  = p ? dW0  : eW0;
        const float* Wih = p ? dWih : eWih;
        const float* Whh = p ? dWhh : eWhh;
        float4 v = make_float4(0.f, 0.f, 0.f, 0.f);
        if (c == 0) {                         // L0 input weights, k-padded
            if (kc < INPUT) {
                v.x = W0[(0 * HID + hh) * INPUT + kc];
                v.y = W0[(1 * HID + hh) * INPUT + kc];
                v.z = W0[(2 * HID + hh) * INPUT + kc];
                v.w = W0[(3 * HID + hh) * INPUT + kc];
            }
        } else {
            const float* W; int k;
            if (c <= 2) {                     // L0 Whh
                W = Whh;
                k = (c - 1) * CHUNK_ROWS + kc;
            } else {
                int l  = (c - 3) / 4 + 1;
                int cc = (c - 3) % 4;
                if (cc < 2) { W = Wih + (size_t)(l - 1) * GATES * HID; k = cc * CHUNK_ROWS + kc; }
                else        { W = Whh + (size_t)l * GATES * HID;       k = (cc - 2) * CHUNK_ROWS + kc; }
            }
            v.x = W[(0 * HID + hh) * HID + k];
            v.y = W[(1 * HID + hh) * HID + k];
            v.z = W[(2 * HID + hh) * HID + k];
            v.w = W[(3 * HID + hh) * HID + k];
        }
        (p ? g_stream_d : g_stream_e)[r] = v;
    }
}

// ---- helpers ----------------------------------------------------------------
__device__ __forceinline__ void ffma2(ull& d, ull a, ull b) {
    asm("fma.rn.f32x2 %0, %1, %2, %0;" : "+l"(d) : "l"(a), "l"(b));
}
__device__ __forceinline__ ull dup2(float a) {
    ull v; asm("mov.b64 %0, {%1, %1};" : "=l"(v) : "f"(a)); return v;
}
__device__ __forceinline__ float2 unpk(ull v) {
    float2 r; asm("mov.b64 {%0, %1}, %2;" : "=f"(r.x), "=f"(r.y) : "l"(v)); return r;
}
// single-MUFU activations via tanh.approx (sm_75+)
__device__ __forceinline__ float tanha(float x) {
    float y; asm("tanh.approx.f32 %0, %1;" : "=f"(y) : "f"(x)); return y;
}
__device__ __forceinline__ float fsig(float x) {
    return fmaf(0.5f, tanha(0.5f * x), 0.5f);
}
__device__ __forceinline__ float ftanh_(float x) {
    return tanha(x);
}
__device__ __forceinline__ uint32_t smem_u32(const void* p) {
    uint32_t a;
    asm("{ .reg .u64 t; cvta.to.shared.u64 t, %1; cvt.u32.u64 %0, t; }"
        : "=r"(a) : "l"(p));
    return a;
}
__device__ __forceinline__ void wait_parity(uint32_t mb, uint32_t parity) {
    asm volatile(
        "{\n\t"
        ".reg .pred P;\n\t"
        "WLOOP_%=:\n\t"
        "mbarrier.try_wait.parity.acquire.cta.shared::cta.b64 P, [%0], %1, 0x989680;\n\t"
        "@P bra WDONE_%=;\n\t"
        "bra WLOOP_%=;\n\t"
        "WDONE_%=:\n\t"
        "}"
        :: "r"(mb), "r"(parity) : "memory");
}

// champion gemv: per k = 2 LDS.128 + 4 dup MOVs + 8 FFMA2
template <int K>
__device__ __forceinline__ void gemv_s(const float4* __restrict__ wslot,
                                       const float* __restrict__ hs,
                                       int hh, int bg, ull acc[8])
{
#pragma unroll 8
    for (int k = 0; k < K; k++) {
        float4 w4 = wslot[k * HID + hh];
        ulonglong2 hv = *(const ulonglong2*)(hs + k * 16 + bg * 4);
        ull wi = dup2(w4.x), wf = dup2(w4.y), wg = dup2(w4.z), wo = dup2(w4.w);
        ffma2(acc[0], wi, hv.x); ffma2(acc[1], wi, hv.y);
        ffma2(acc[2], wf, hv.x); ffma2(acc[3], wf, hv.y);
        ffma2(acc[4], wg, hv.x); ffma2(acc[5], wg, hv.y);
        ffma2(acc[6], wo, hv.x); ffma2(acc[7], wo, hv.y);
    }
}

// ---- smem layout ------------------------------------------------------------
#define RING_SZ   (NSLOT * CHUNK_BYTES)     // 163840
#define MBAR_B    RING_SZ
#define FB_B      (RING_SZ + 64)
#define HD_F      0                          // [2][4][64][16]
#define SZ_HD     (2 * LAYERS * HID * 16)    // 8192
#define IND_F     (HD_F + SZ_HD)
#define LW_F      (IND_F + 128)
#define LB_F      (LW_F + HID * INPUT)
#define BIAS_F    (LB_F + 8)                 // ull[2][4][64][4] = 4096 floats
#define SMEM_TOTAL_B (FB_B + (BIAS_F + 4096) * 4)

__global__ void __launch_bounds__(NTHR, 1)
lstm36206574305735_main(const float* __restrict__ x,
                        const float* __restrict__ eB,
                        const float* __restrict__ dB,
                        const float* __restrict__ linW,
                        const float* __restrict__ linB,
                        float* __restrict__ out)
{
    extern __shared__ char sm[];
    const uint32_t ring_u = smem_u32(sm);
    const uint32_t mbar_u = ring_u + MBAR_B;
    float* fb   = (float*)(sm + FB_B);
    float* hd   = fb + HD_F;
    float* ind  = fb + IND_F;
    float* lw_s = fb + LW_F;
    float* lb_s = fb + LB_F;
    ull*   bias = (ull*)(fb + BIAS_F);

    const int tid = threadIdx.x;
    const int hh  = tid >> 2;
    const int bg  = tid & 3;
    const int b0  = blockIdx.x * NB;

    if (tid == 0) {
        for (int s = 0; s < NSLOT; s++)
            asm volatile("mbarrier.init.shared.b64 [%0], 1;"
                         :: "r"(mbar_u + s * 8) : "memory");
        asm volatile("fence.proxy.async.shared::cta;" ::: "memory");
    }
    for (int i = tid; i < SZ_HD; i += NTHR) hd[i] = 0.0f;
    for (int i = tid; i < 128; i += NTHR) ind[i] = 0.0f;
    for (int i = tid; i < HID * INPUT; i += NTHR) {
        int h2 = i / INPUT, ii2 = i % INPUT;
        lw_s[h2 * INPUT + ii2] = linW[ii2 * HID + h2];
    }
    if (tid < INPUT) lb_s[tid] = linB[tid];
    for (int u = tid; u < 2 * LAYERS * HID; u += NTHR) {
        int phase = u >> 8, l = (u >> 6) & 3, hx = u & 63;
        const float* B = phase ? dB : eB;
        bias[u * 4 + 0] = dup2(B[l * GATES + hx]);
        bias[u * 4 + 1] = dup2(B[l * GATES + HID + hx]);
        bias[u * 4 + 2] = dup2(B[l * GATES + 2 * HID + hx]);
        bias[u * 4 + 3] = dup2(B[l * GATES + 3 * HID + hx]);
    }
    __syncthreads();

    auto issue_one = [&](int G) {
        if (G >= TOTALC) return;
        int s = G % NSLOT;
        const float4* src = (G < 120 * CPS ? g_stream_e : g_stream_d)
                            + (size_t)(G % CPS) * CHUNK_F4;
        uint32_t mb = mbar_u + s * 8;
        asm volatile("mbarrier.arrive.expect_tx.shared.b64 _, [%0], %1;"
                     :: "r"(mb), "r"((uint32_t)CHUNK_BYTES) : "memory");
        asm volatile("cp.async.bulk.shared::cluster.global.mbarrier::complete_tx::bytes "
                     "[%0], [%1], %2, [%3];"
                     :: "r"(ring_u + (uint32_t)s * CHUNK_BYTES), "l"(src),
                        "r"((uint32_t)CHUNK_BYTES), "r"(mb) : "memory");
    };
    if (tid == 0)
        for (int g = 0; g < NSLOT; g++) issue_one(g);

    int Gi = NSLOT, cap = NSLOT, Cg = 0;
    unsigned par = 0;

    auto next_chunk = [&]() -> const float4* {
        int s = Cg % NSLOT;
        wait_parity(mbar_u + s * 8, (par >> s) & 1u);
        par ^= (1u << s);
        Cg++;
        return (const float4*)(sm + (size_t)s * CHUNK_BYTES);
    };
    auto barrier_issue = [&](int add) {
        __syncthreads();
        cap += add;
        if (tid == 0)
            for (; Gi < cap; Gi++) issue_one(Gi);
        else
            Gi = cap;
    };

    float c_reg[LAYERS][4];
#pragma unroll
    for (int l = 0; l < LAYERS; l++)
#pragma unroll
        for (int bi = 0; bi < 4; bi++) c_reg[l][bi] = 0.0f;

    const int  bb  = tid / INPUT;
    const int  ii  = tid % INPUT;
    const bool isx = tid < INPUT * NB;
    float xreg = 0.0f;
    if (isx) xreg = x[(size_t)(b0 + bb) * INPUT + ii];

    auto do_layer = [&](int phase, int w, int l, int add, bool isL0) {
        const ull* bv = bias + ((phase * LAYERS + l) * HID + hh) * 4;
        ull acc[8];
        acc[0] = acc[1] = bv[0];
        acc[2] = acc[3] = bv[1];
        acc[4] = acc[5] = bv[2];
        acc[6] = acc[7] = bv[3];

        if (isL0) {
            const float4* wp = next_chunk(); gemv_s<8>(wp, ind, hh, bg, acc);
        } else {
            const float* hp = hd + ((w * LAYERS + (l - 1)) * HID) * 16;
            { const float4* wp = next_chunk(); gemv_s<32>(wp, hp,       hh, bg, acc); }
            { const float4* wp = next_chunk(); gemv_s<32>(wp, hp + 512, hh, bg, acc); }
        }
        const float* hl = hd + (((w ^ 1) * LAYERS + l) * HID) * 16;
        { const float4* wp = next_chunk(); gemv_s<32>(wp, hl,       hh, bg, acc); }
        { const float4* wp = next_chunk(); gemv_s<32>(wp, hl + 512, hh, bg, acc); }

        float2 ai0 = unpk(acc[0]), ai1 = unpk(acc[1]);
        float2 af0 = unpk(acc[2]), af1 = unpk(acc[3]);
        float2 ag0 = unpk(acc[4]), ag1 = unpk(acc[5]);
        float2 ao0 = unpk(acc[6]), ao1 = unpk(acc[7]);
        float ai[4] = {ai0.x, ai0.y, ai1.x, ai1.y};
        float af[4] = {af0.x, af0.y, af1.x, af1.y};
        float ag[4] = {ag0.x, ag0.y, ag1.x, ag1.y};
        float ao[4] = {ao0.x, ao0.y, ao1.x, ao1.y};
        float hout[4];
#pragma unroll
        for (int bi = 0; bi < 4; bi++) {
            float c = fmaf(fsig(af[bi]), c_reg[l][bi],
                           fsig(ai[bi]) * ftanh_(ag[bi]));
            c_reg[l][bi] = c;
            hout[bi] = fsig(ao[bi]) * ftanh_(c);
        }
        float* hrow = hd + ((w * LAYERS + l) * HID + hh) * 16 + bg * 4;
        *(float4*)hrow = make_float4(hout[0], hout[1], hout[2], hout[3]);
        barrier_issue(add);
    };

    // -------- encoder --------
    for (int t = 0; t < SEQ_LEN; t++) {
        if (isx) {
            ind[ii * 16 + bb] = xreg;
            if (t + 1 < SEQ_LEN)
                xreg = x[((size_t)(t + 1) * BATCH + b0 + bb) * INPUT + ii];
        }
        __syncthreads();
        int w = t & 1;
        do_layer(0, w, 0, t == 0 ? 3 : 4, true);
        do_layer(0, w, 1, 4, false);
        do_layer(0, w, 2, 4, false);
        do_layer(0, w, 3, 3, false);
    }
    // ind holds x[SEQ_LEN-1] — decoder seed

    // -------- decoder --------
    for (int t = 0; t < TLEN; t++) {
        int w = t & 1;   // SEQ_LEN even
        do_layer(1, w, 0, 4, true);
        do_layer(1, w, 1, 4, false);
        do_layer(1, w, 2, 4, false);
        do_layer(1, w, 3, 3, false);

        if (isx) {
            const float* htop = hd + ((w * LAYERS + (LAYERS - 1)) * HID) * 16;
            float v = lb_s[ii];
#pragma unroll 8
            for (int h2 = 0; h2 < HID; h2++)
                v += lw_s[h2 * INPUT + ii] * htop[h2 * 16 + bb];
            out[((size_t)t * BATCH + b0 + bb) * INPUT + ii] = v;
            ind[ii * 16 + bb] = v;
        }
        __syncthreads();
    }
}

extern "C" void kernel_launch(void* const* d_in, const int* in_sizes, int n_in,
                              void* d_out, int out_size)
{
    const float* x    = (const float*)d_in[0];
    const float* eW0  = (const float*)d_in[1];
    const float* eWih = (const float*)d_in[2];
    const float* eWhh = (const float*)d_in[3];
    const float* eB   = (const float*)d_in[4];
    const float* dW0  = (const float*)d_in[5];
    const float* dWih = (const float*)d_in[6];
    const float* dWhh = (const float*)d_in[7];
    const float* dB   = (const float*)d_in[8];
    const float* linW = (const float*)d_in[9];
    const float* linB = (const float*)d_in[10];
    float* out = (float*)d_out;

    lstm36206574305735_pack<<<240, 256>>>(eW0, eWih, eWhh, dW0, dWih, dWhh);

    cudaFuncSetAttribute(lstm36206574305735_main,
                         cudaFuncAttributeMaxDynamicSharedMemorySize, SMEM_TOTAL_B);
    lstm36206574305735_main<<<NCTA, NTHR, SMEM_TOTAL_B>>>(x, eB, dB, linW, linB, out);
}

// round 16
// speedup vs baseline: 2.0858x; 1.9961x over previous
#include <cuda_runtime.h>
#include <cuda_fp16.h>
#include <cstdint>

#define SEQ_LEN  120
#define BATCH    2048
#define INPUT    6
#define HID      64
#define GATES    256
#define LAYERS   4
#define TLEN     120
#define NB       16
#define NCTA     (BATCH / NB)   // 128
#define NTHR     256

#define KP       136            // B row pitch in halves (bank-conflict-free)
#define NSLOT    5
#define SLOT_B   32768
#define CPS      16             // 4 chunks per layer: hiA,hiB,loA,loB
#define TOTALC   (240 * CPS)
// chunk sizes: L0 chunks (c%16<4): 8mt*5ks*512B = 20480 ; else 8mt*8ks*512B = 32768
#define PHASE_HALVES 237568     // (4*20480 + 12*32768)/2

typedef unsigned long long ull;

__device__ __half g_hs_e[PHASE_HALVES];
__device__ __half g_hs_d[PHASE_HALVES];

__host__ __device__ __forceinline__ int chunk_off_h(int c) {
    return (c < 4) ? c * 10240 : 40960 + (c - 4) * 16384;
}

// fragment-order pack: chunk c = l*4+q (q0=hiA,q1=hiB,q2=loA,q3=loB)
// within chunk: [mtl 0..7][ks][lane 0..31][8 halves = a0lo,a0hi,a1lo,a1hi,a2lo,a2hi,a3lo,a3hi]
// A row-major m16k16 frag: a0:(r=mt*16+lane/4, k=ks*16+(lane%4)*2+{0,1})
//                          a1:(r+8, same k)  a2:(r, k+8+{0,1})  a3:(r+8, k+8)
// A rows gate-major: row = gate*64+hid. L0 k: [0..15]=x(pad 6), [16..79]=Whh0. l>=1: [0..63]=Wih, [64..127]=Whh.
__global__ void lstm36206574305735_pack(
    const float* __restrict__ eW0, const float* __restrict__ eWih,
    const float* __restrict__ eWhh, const float* __restrict__ dW0,
    const float* __restrict__ dWih, const float* __restrict__ dWhh)
{
    const int tot = 2 * PHASE_HALVES;
    for (int idx = blockIdx.x * blockDim.x + threadIdx.x; idx < tot;
         idx += gridDim.x * blockDim.x) {
        int p   = idx / PHASE_HALVES;
        int hix = idx % PHASE_HALVES;
        int c, e, KS;
        if (hix < 40960) { c = hix / 10240; e = hix % 10240; KS = 5; }
        else { int r2 = hix - 40960; c = 4 + r2 / 16384; e = r2 % 16384; KS = 8; }
        int l = c >> 2, q = c & 3;
        int mtl = e / (KS * 256);
        int rem = e % (KS * 256);
        int ks  = rem / 256;
        int le  = rem & 255;
        int lane = le >> 3;
        int ri   = le & 7;
        int mt = (q & 1) * 8 + mtl;
        int rg = ri >> 1, hl = ri & 1;
        int row = mt * 16 + (lane >> 2) + ((rg & 1) ? 8 : 0);
        int kk  = ks * 16 + (lane & 3) * 2 + ((rg & 2) ? 8 : 0) + hl;
        const float* W0  = p ? dW0  : eW0;
        const float* Wih = p ? dWih : eWih;
        const float* Whh = p ? dWhh : eWhh;
        float w = 0.0f;
        if (l == 0) {
            if (kk < 16) { if (kk < INPUT) w = W0[row * INPUT + kk]; }
            else w = Whh[row * HID + (kk - 16)];
        } else {
            if (kk < 64) w = Wih[((size_t)(l - 1) * GATES + row) * HID + kk];
            else         w = Whh[((size_t)l * GATES + row) * HID + (kk - 64)];
        }
        __half hi = __float2half(w);
        __half v  = (q < 2) ? hi : __float2half(w - __half2float(hi));
        (p ? g_hs_d : g_hs_e)[chunk_off_h(c) + e] = v;
    }
}

// ---- helpers ----------------------------------------------------------------
__device__ __forceinline__ float tanha(float x) {
    float y; asm("tanh.approx.f32 %0, %1;" : "=f"(y) : "f"(x)); return y;
}
__device__ __forceinline__ float fsig(float x) {
    return fmaf(0.5f, tanha(0.5f * x), 0.5f);
}
__device__ __forceinline__ uint32_t smem_u32(const void* p) {
    uint32_t a;
    asm("{ .reg .u64 t; cvta.to.shared.u64 t, %1; cvt.u32.u64 %0, t; }"
        : "=r"(a) : "l"(p));
    return a;
}
__device__ __forceinline__ void wait_parity(uint32_t mb, uint32_t parity) {
    asm volatile(
        "{\n\t"
        ".reg .pred P;\n\t"
        "WLOOP_%=:\n\t"
        "mbarrier.try_wait.parity.acquire.cta.shared::cta.b64 P, [%0], %1, 0x989680;\n\t"
        "@P bra WDONE_%=;\n\t"
        "bra WLOOP_%=;\n\t"
        "WDONE_%=:\n\t"
        "}"
        :: "r"(mb), "r"(parity) : "memory");
}
__device__ __forceinline__ void hmma(float acc[4], const uint32_t a[4],
                                     uint32_t b0, uint32_t b1) {
    asm volatile(
        "mma.sync.aligned.m16n8k16.row.col.f32.f16.f16.f32 "
        "{%0,%1,%2,%3}, {%4,%5,%6,%7}, {%8,%9}, {%0,%1,%2,%3};"
        : "+f"(acc[0]), "+f"(acc[1]), "+f"(acc[2]), "+f"(acc[3])
        : "r"(a[0]), "r"(a[1]), "r"(a[2]), "r"(a[3]), "r"(b0), "r"(b1));
}

// ---- smem layout (bytes) ------------------------------------------------------
#define RING_SZ  (NSLOT * SLOT_B)          // 163840
#define BH_B     RING_SZ                   // __half [4][16][KP] = 17408
#define BL_B     (BH_B + 4 * 16 * KP * 2)  // 181248
#define SB_B     (BL_B + 4 * 16 * KP * 2)  // 198656 ; f32 [256][20] = 20480
#define BIAS_B   (SB_B + 256 * 20 * 4)     // 219136 ; f32 [2][4][256] = 8192
#define LW_B     (BIAS_B + 8192)           // 227328 ; f32 [64][6]
#define LB_B     (LW_B + 1536)             // 228864
#define MBAR_B   (LB_B + 32)               // 228896 ; 5 x 8B
#define SMEM_TOTAL_B 228944

__global__ void __launch_bounds__(NTHR, 1)
lstm36206574305735_main(const float* __restrict__ x,
                        const float* __restrict__ eB,
                        const float* __restrict__ dB,
                        const float* __restrict__ linW,
                        const float* __restrict__ linB,
                        float* __restrict__ out)
{
    extern __shared__ char sm[];
    const uint32_t base_u = smem_u32(sm);
    const uint32_t mbar_u = base_u + MBAR_B;
    __half* BH   = (__half*)(sm + BH_B);
    __half* BL   = (__half*)(sm + BL_B);
    float* sbuf  = (float*)(sm + SB_B);
    float* bias_s = (float*)(sm + BIAS_B);
    float* lw_s  = (float*)(sm + LW_B);
    float* lb_s  = (float*)(sm + LB_B);

    const int tid  = threadIdx.x;
    const int w    = tid >> 5;
    const int lane = tid & 31;
    const int hh   = tid >> 2;
    const int bg   = tid & 3;
    const int b0   = blockIdx.x * NB;

    if (tid == 0) {
        for (int s = 0; s < NSLOT; s++)
            asm volatile("mbarrier.init.shared.b64 [%0], 1;"
                         :: "r"(mbar_u + s * 8) : "memory");
        asm volatile("fence.proxy.async.shared::cta;" ::: "memory");
    }
    // zero B arrays (h(-1)=0, x padding)
    for (int i = tid; i < (2 * 4 * 16 * KP * 2) / 4; i += NTHR)
        ((uint32_t*)(sm + BH_B))[i] = 0u;
    for (int u = tid; u < 2 * LAYERS * GATES; u += NTHR) {
        int p = u / (LAYERS * GATES), r = u % (LAYERS * GATES);
        bias_s[u] = (p ? dB : eB)[r];
    }
    for (int i = tid; i < HID * INPUT; i += NTHR) {
        int h2 = i / INPUT, ii2 = i % INPUT;
        lw_s[h2 * INPUT + ii2] = linW[ii2 * HID + h2];
    }
    if (tid < INPUT) lb_s[tid] = linB[tid];
    __syncthreads();

    auto issue_one = [&](int G) {
        if (G >= TOTALC) return;
        int s = G % NSLOT;
        int cc = G % CPS;
        const __half* src = ((G < 120 * CPS) ? g_hs_e : g_hs_d) + chunk_off_h(cc);
        uint32_t bytes = (cc < 4) ? 20480u : 32768u;
        uint32_t mb = mbar_u + s * 8;
        asm volatile("mbarrier.arrive.expect_tx.shared.b64 _, [%0], %1;"
                     :: "r"(mb), "r"(bytes) : "memory");
        asm volatile("cp.async.bulk.shared::cluster.global.mbarrier::complete_tx::bytes "
                     "[%0], [%1], %2, [%3];"
                     :: "r"(base_u + (uint32_t)s * SLOT_B), "l"(src),
                        "r"(bytes), "r"(mb) : "memory");
    };
    auto lw = [&](int G) {
        if (G >= TOTALC) return;
        wait_parity(mbar_u + (G % NSLOT) * 8, (uint32_t)((G / NSLOT) & 1));
    };
    if (tid == 0)
        for (int g = 0; g < NSLOT; g++) issue_one(g);
    int Gi = NSLOT;

    float c_reg[LAYERS][4];
#pragma unroll
    for (int l = 0; l < LAYERS; l++)
#pragma unroll
        for (int bi = 0; bi < 4; bi++) c_reg[l][bi] = 0.0f;

    const int  bb  = tid / INPUT;
    const int  ii  = tid % INPUT;
    const bool isx = tid < INPUT * NB;
    float xreg = 0.0f;
    if (isx) xreg = x[(size_t)(b0 + bb) * INPUT + ii];

    const int nb = lane >> 2;          // B frag n within tile
    const int kb = (lane & 3) * 2;     // B frag k base
    int G = 0;

    for (int t = 0; t < SEQ_LEN + TLEN; t++) {
        const int p = (t >= SEQ_LEN) ? 1 : 0;

        // stage x(t) (encoder); decoder feedback staged at projection below
        if (t < SEQ_LEN && isx) {
            __half hi = __float2half(xreg);
            __half lo = __float2half(xreg - __half2float(hi));
            BH[bb * KP + ii] = hi;
            BL[bb * KP + ii] = lo;
            if (t + 1 < SEQ_LEN)
                xreg = x[((size_t)(t + 1) * BATCH + b0 + bb) * INPUT + ii];
        }

#pragma unroll
        for (int l = 0; l < LAYERS; l++) {
            const int KS = (l == 0) ? 5 : 8;

            if (tid == 0) { lw(G); lw(G + 1); lw(G + 2); lw(G + 3); }
            __syncthreads();

            // ---- MMA: this warp's chunks (warps 0-3: A-half, 4-7: B-half)
            const char* slotHi = sm + (size_t)((G + (w >> 2)) % NSLOT) * SLOT_B;
            const char* slotLo = sm + (size_t)((G + 2 + (w >> 2)) % NSLOT) * SLOT_B;
            const __half* BhL = BH + l * 16 * KP;
            const __half* BlL = BL + l * 16 * KP;

            float acc[2][2][4];
#pragma unroll
            for (int mi = 0; mi < 2; mi++)
#pragma unroll
                for (int ni = 0; ni < 2; ni++)
#pragma unroll
                    for (int q = 0; q < 4; q++) acc[mi][ni][q] = 0.0f;

            for (int ks = 0; ks < KS; ks++) {
                uint32_t bh[2][2], bl[2][2];
#pragma unroll
                for (int ni = 0; ni < 2; ni++) {
                    int nrow = ni * 8 + nb;
                    int k0 = ks * 16 + kb;
                    bh[ni][0] = *(const uint32_t*)&BhL[nrow * KP + k0];
                    bh[ni][1] = *(const uint32_t*)&BhL[nrow * KP + k0 + 8];
                    bl[ni][0] = *(const uint32_t*)&BlL[nrow * KP + k0];
                    bl[ni][1] = *(const uint32_t*)&BlL[nrow * KP + k0 + 8];
                }
#pragma unroll
                for (int mi = 0; mi < 2; mi++) {
                    int mtl = (w & 3) * 2 + mi;
                    const uint32_t* ah = (const uint32_t*)
                        (slotHi + ((size_t)(mtl * KS + ks) * 32 + lane) * 16);
                    const uint32_t* al = (const uint32_t*)
                        (slotLo + ((size_t)(mtl * KS + ks) * 32 + lane) * 16);
                    uint32_t ahr[4] = {ah[0], ah[1], ah[2], ah[3]};
                    uint32_t alr[4] = {al[0], al[1], al[2], al[3]};
#pragma unroll
                    for (int ni = 0; ni < 2; ni++) {
                        hmma(acc[mi][ni], ahr, bh[ni][0], bh[ni][1]);
                        hmma(acc[mi][ni], ahr, bl[ni][0], bl[ni][1]);
                        hmma(acc[mi][ni], alr, bh[ni][0], bh[ni][1]);
                    }
                }
            }

            // ---- store gates to sbuf [256 rows][20]
#pragma unroll
            for (int mi = 0; mi < 2; mi++) {
                int row0 = (w * 2 + mi) * 16 + (lane >> 2);
#pragma unroll
                for (int ni = 0; ni < 2; ni++) {
                    int col = ni * 8 + (lane & 3) * 2;
                    *(float2*)&sbuf[row0 * 20 + col] =
                        make_float2(acc[mi][ni][0], acc[mi][ni][1]);
                    *(float2*)&sbuf[(row0 + 8) * 20 + col] =
                        make_float2(acc[mi][ni][2], acc[mi][ni][3]);
                }
            }
            __syncthreads();
            if (tid == 0) { issue_one(Gi); issue_one(Gi + 1); issue_one(Gi + 2); issue_one(Gi + 3); }
            Gi += 4;

            // ---- cell epilogue (fp32 exact bias, approx activations)
            {
                float4 zi4 = *(float4*)&sbuf[(0 * HID + hh) * 20 + bg * 4];
                float4 zf4 = *(float4*)&sbuf[(1 * HID + hh) * 20 + bg * 4];
                float4 zg4 = *(float4*)&sbuf[(2 * HID + hh) * 20 + bg * 4];
                float4 zo4 = *(float4*)&sbuf[(3 * HID + hh) * 20 + bg * 4];
                float b_i = bias_s[(p * LAYERS + l) * GATES + 0 * HID + hh];
                float b_f = bias_s[(p * LAYERS + l) * GATES + 1 * HID + hh];
                float b_g = bias_s[(p * LAYERS + l) * GATES + 2 * HID + hh];
                float b_o = bias_s[(p * LAYERS + l) * GATES + 3 * HID + hh];
                float zi[4] = {zi4.x, zi4.y, zi4.z, zi4.w};
                float zf[4] = {zf4.x, zf4.y, zf4.z, zf4.w};
                float zg[4] = {zg4.x, zg4.y, zg4.z, zg4.w};
                float zo[4] = {zo4.x, zo4.y, zo4.z, zo4.w};
                int koff_own = ((l == 0) ? 16 : 64) + hh;
#pragma unroll
                for (int bi = 0; bi < 4; bi++) {
                    int n = bg * 4 + bi;
                    float c = fmaf(fsig(zf[bi] + b_f), c_reg[l][bi],
                                   fsig(zi[bi] + b_i) * tanha(zg[bi] + b_g));
                    c_reg[l][bi] = c;
                    float hv = fsig(zo[bi] + b_o) * tanha(c);
                    __half hi = __float2half(hv);
                    __half lo = __float2half(hv - __half2float(hi));
                    BH[(l * 16 + n) * KP + koff_own] = hi;
                    BL[(l * 16 + n) * KP + koff_own] = lo;
                    if (l < 3) {
                        BH[((l + 1) * 16 + n) * KP + hh] = hi;
                        BL[((l + 1) * 16 + n) * KP + hh] = lo;
                    }
                }
            }
            __syncthreads();
            G += 4;
        }

        // ---- decoder projection + feedback (h3 = BH3+BL3 at k=64+h)
        if (t >= SEQ_LEN && isx) {
            const __half* bh3 = BH + (3 * 16 + bb) * KP + 64;
            const __half* bl3 = BL + (3 * 16 + bb) * KP + 64;
            float v = lb_s[ii];
#pragma unroll 8
            for (int h4 = 0; h4 < HID; h4++)
                v += lw_s[h4 * INPUT + ii]
                     * (__half2float(bh3[h4]) + __half2float(bl3[h4]));
            out[((size_t)(t - SEQ_LEN) * BATCH + b0 + bb) * INPUT + ii] = v;
            __half hi = __float2half(v);
            __half lo = __float2half(v - __half2float(hi));
            BH[bb * KP + ii] = hi;
            BL[bb * KP + ii] = lo;
        }
        // ordered before next step's L0 MMA by the L0 entry __syncthreads
    }
}

extern "C" void kernel_launch(void* const* d_in, const int* in_sizes, int n_in,
                              void* d_out, int out_size)
{
    const float* x    = (const float*)d_in[0];
    const float* eW0  = (const float*)d_in[1];
    const float* eWih = (const float*)d_in[2];
    const float* eWhh = (const float*)d_in[3];
    const float* eB   = (const float*)d_in[4];
    const float* dW0  = (const float*)d_in[5];
    const float* dWih = (const float*)d_in[6];
    const float* dWhh = (const float*)d_in[7];
    const float* dB   = (const float*)d_in[8];
    const float* linW = (const float*)d_in[9];
    const float* linB = (const float*)d_in[10];
    float* out = (float*)d_out;

    lstm36206574305735_pack<<<464, 256>>>(eW0, eWih, eWhh, dW0, dWih, dWhh);

    cudaFuncSetAttribute(lstm36206574305735_main,
                         cudaFuncAttributeMaxDynamicSharedMemorySize, SMEM_TOTAL_B);
    lstm36206574305735_main<<<NCTA, NTHR, SMEM_TOTAL_B>>>(x, eB, dB, linW, linB, out);
}